// round 13
// baseline (speedup 1.0000x reference)
#include <cuda_runtime.h>
#include <cstdint>

#define N_LEVELS 12
#define LOG2_T 19
#define T_SIZE (1u << LOG2_T)
#define T_MASK (T_SIZE - 1u)
#define N_PTS 1048576

#define LOW_LEVELS 8   // sector-aligned output split: 64B low / 32B high

#define BIN_BITS 5
#define BIN_RES (1 << BIN_BITS)      // 32
#define NBINS (1 << (3 * BIN_BITS))  // 32768
#define BIN_CAP 128
#define PAD_SLOTS (NBINS * BIN_CAP)  // 4M

#define P1 2654435761u
#define P2 805459861u

__constant__ float c_res[N_LEVELS] = {
    16.f, 22.f, 30.f, 42.f, 58.f, 80.f, 110.f, 152.f, 210.f, 290.f, 400.f, 553.f
};

__device__ uint32_t g_cursor[NBINS];
__device__ float4   g_pad[PAD_SLOTS];

// ---------------------------------------------------------------------------
__device__ __forceinline__ uint32_t expand5(uint32_t v) {
    v = (v | (v << 8)) & 0x0000F00Fu;
    v = (v | (v << 4)) & 0x000C30C3u;
    v = (v | (v << 2)) & 0x00249249u;
    return v;
}

__device__ __forceinline__ uint32_t bin_id(float px, float py, float pz) {
    uint32_t bx = min((uint32_t)(px * BIN_RES), (uint32_t)(BIN_RES - 1));
    uint32_t by = min((uint32_t)(py * BIN_RES), (uint32_t)(BIN_RES - 1));
    uint32_t bz = min((uint32_t)(pz * BIN_RES), (uint32_t)(BIN_RES - 1));
    return expand5(bx) | (expand5(by) << 1) | (expand5(bz) << 2);
}

// ---------------------------------------------------------------------------
__global__ void zero_cursor_kernel() {
    int i = blockIdx.x * blockDim.x + threadIdx.x;
    if (i < NBINS) g_cursor[i] = 0u;
}

__global__ __launch_bounds__(256) void scatter_kernel(const float* __restrict__ x) {
    int n = blockIdx.x * blockDim.x + threadIdx.x;
    if (n >= N_PTS) return;
    float px = x[n * 3 + 0];
    float py = x[n * 3 + 1];
    float pz = x[n * 3 + 2];
    uint32_t b = bin_id(px, py, pz);
    uint32_t pos = atomicAdd(&g_cursor[b], 1u);
    if (pos < BIN_CAP)
        g_pad[b * BIN_CAP + pos] = make_float4(px, py, pz, __int_as_float(n));
}

// ---------------------------------------------------------------------------
__device__ __forceinline__ void tri_weights(
    float wx, float wy, float wz,
    float& w000, float& w100, float& w010, float& w110,
    float& w001, float& w101, float& w011, float& w111)
{
    const float ux = 1.f - wx;
    const float uy = 1.f - wy;
    const float uz = 1.f - wz;
    const float w00 = uy * uz;
    const float w10 = wy * uz;
    const float w01 = uy * wz;
    const float w11 = wy * wz;
    w000 = ux * w00;  w100 = wx * w00;
    w010 = ux * w10;  w110 = wx * w10;
    w001 = ux * w01;  w101 = wx * w01;
    w011 = ux * w11;  w111 = wx * w11;
}

// Simple 8-gather trilerp — for levels whose warps already share cache lines.
__device__ __forceinline__ void level_lerp(
    const float* __restrict__ tables, int l,
    float px, float py, float pz, float& a0, float& a1)
{
    const float res = c_res[l];
    const float sx = px * res, sy = py * res, sz = pz * res;
    const float fx = floorf(sx), fy = floorf(sy), fz = floorf(sz);
    const float wx = sx - fx, wy = sy - fy, wz = sz - fz;

    const uint32_t x0 = (uint32_t)fx;
    const uint32_t hy0 = (uint32_t)fy * P1;
    const uint32_t hy1 = hy0 + P1;
    const uint32_t hz0 = (uint32_t)fz * P2;
    const uint32_t hz1 = hz0 + P2;
    const uint32_t hx0 = x0;
    const uint32_t hx1 = x0 + 1u;

    const float2* __restrict__ tab =
        reinterpret_cast<const float2*>(tables) + (size_t)l * T_SIZE;

    const float2 f000 = __ldg(&tab[(hx0 ^ hy0 ^ hz0) & T_MASK]);
    const float2 f100 = __ldg(&tab[(hx1 ^ hy0 ^ hz0) & T_MASK]);
    const float2 f010 = __ldg(&tab[(hx0 ^ hy1 ^ hz0) & T_MASK]);
    const float2 f110 = __ldg(&tab[(hx1 ^ hy1 ^ hz0) & T_MASK]);
    const float2 f001 = __ldg(&tab[(hx0 ^ hy0 ^ hz1) & T_MASK]);
    const float2 f101 = __ldg(&tab[(hx1 ^ hy0 ^ hz1) & T_MASK]);
    const float2 f011 = __ldg(&tab[(hx0 ^ hy1 ^ hz1) & T_MASK]);
    const float2 f111 = __ldg(&tab[(hx1 ^ hy1 ^ hz1) & T_MASK]);

    float w000, w100, w010, w110, w001, w101, w011, w111;
    tri_weights(wx, wy, wz, w000, w100, w010, w110, w001, w101, w011, w111);

    a0 = w000 * f000.x;            a1 = w000 * f000.y;
    a0 = fmaf(w100, f100.x, a0);   a1 = fmaf(w100, f100.y, a1);
    a0 = fmaf(w010, f010.x, a0);   a1 = fmaf(w010, f010.y, a1);
    a0 = fmaf(w110, f110.x, a0);   a1 = fmaf(w110, f110.y, a1);
    a0 = fmaf(w001, f001.x, a0);   a1 = fmaf(w001, f001.y, a1);
    a0 = fmaf(w101, f101.x, a0);   a1 = fmaf(w101, f101.y, a1);
    a0 = fmaf(w011, f011.x, a0);   a1 = fmaf(w011, f011.y, a1);
    a0 = fmaf(w111, f111.x, a0);   a1 = fmaf(w111, f111.y, a1);
}

// Paired-gather trilerp — for levels with divergent (random-like) warp access.
// Even x0: h(dx=1) = h(dx=0)^1 -> one aligned float4 per (dy,dz) (4 loads).
__device__ __forceinline__ void level_lerp_paired(
    const float* __restrict__ tables, int l,
    float px, float py, float pz, float& a0, float& a1)
{
    const float res = c_res[l];
    const float sx = px * res, sy = py * res, sz = pz * res;
    const float fx = floorf(sx), fy = floorf(sy), fz = floorf(sz);
    const float wx = sx - fx, wy = sy - fy, wz = sz - fz;

    const uint32_t x0 = (uint32_t)fx;
    const uint32_t hy0 = (uint32_t)fy * P1;
    const uint32_t hy1 = hy0 + P1;
    const uint32_t hz0 = (uint32_t)fz * P2;
    const uint32_t hz1 = hz0 + P2;

    const uint32_t s00 = hy0 ^ hz0;
    const uint32_t s10 = hy1 ^ hz0;
    const uint32_t s01 = hy0 ^ hz1;
    const uint32_t s11 = hy1 ^ hz1;

    const float2* __restrict__ tab =
        reinterpret_cast<const float2*>(tables) + (size_t)l * T_SIZE;

    float2 f000, f100, f010, f110, f001, f101, f011, f111;

    if ((x0 & 1u) == 0u) {
        const float4* __restrict__ tab4 = reinterpret_cast<const float4*>(tab);
#define PAIR4(s, lo, hi)                                                    \
        {                                                                   \
            const uint32_t h = (x0 ^ (s)) & T_MASK;                         \
            const float4 v = __ldg(&tab4[h >> 1]);                          \
            const float2 e0 = make_float2(v.x, v.y);                        \
            const float2 e1 = make_float2(v.z, v.w);                        \
            if (h & 1u) { lo = e1; hi = e0; } else { lo = e0; hi = e1; }    \
        }
        PAIR4(s00, f000, f100)
        PAIR4(s10, f010, f110)
        PAIR4(s01, f001, f101)
        PAIR4(s11, f011, f111)
#undef PAIR4
    } else {
        const uint32_t hx0 = x0;
        const uint32_t hx1 = x0 + 1u;
        f000 = __ldg(&tab[(hx0 ^ s00) & T_MASK]);
        f100 = __ldg(&tab[(hx1 ^ s00) & T_MASK]);
        f010 = __ldg(&tab[(hx0 ^ s10) & T_MASK]);
        f110 = __ldg(&tab[(hx1 ^ s10) & T_MASK]);
        f001 = __ldg(&tab[(hx0 ^ s01) & T_MASK]);
        f101 = __ldg(&tab[(hx1 ^ s01) & T_MASK]);
        f011 = __ldg(&tab[(hx0 ^ s11) & T_MASK]);
        f111 = __ldg(&tab[(hx1 ^ s11) & T_MASK]);
    }

    float w000, w100, w010, w110, w001, w101, w011, w111;
    tri_weights(wx, wy, wz, w000, w100, w010, w110, w001, w101, w011, w111);

    a0 = w000 * f000.x;            a1 = w000 * f000.y;
    a0 = fmaf(w100, f100.x, a0);   a1 = fmaf(w100, f100.y, a1);
    a0 = fmaf(w010, f010.x, a0);   a1 = fmaf(w010, f010.y, a1);
    a0 = fmaf(w110, f110.x, a0);   a1 = fmaf(w110, f110.y, a1);
    a0 = fmaf(w001, f001.x, a0);   a1 = fmaf(w001, f001.y, a1);
    a0 = fmaf(w101, f101.x, a0);   a1 = fmaf(w101, f101.y, a1);
    a0 = fmaf(w011, f011.x, a0);   a1 = fmaf(w011, f011.y, a1);
    a0 = fmaf(w111, f111.x, a0);   a1 = fmaf(w111, f111.y, a1);
}

// Levels 0..7 over padded buckets (sorted). 0-5 simple (lines shared in-warp),
// 6-7 paired (warp span >> cell size -> divergent). Writes 64B sectors 0,1.
__global__ __launch_bounds__(256) void low_kernel(
    const float* __restrict__ tables, float* __restrict__ out)
{
    int j = blockIdx.x * blockDim.x + threadIdx.x;
    const uint32_t bin = (uint32_t)j >> 7;
    const uint32_t slot = (uint32_t)j & (BIN_CAP - 1);

    const uint32_t cnt = g_cursor[bin];
    if (slot >= cnt) return;

    const float4 s = g_pad[j];
    const float px = s.x, py = s.y, pz = s.z;
    const int n = __float_as_int(s.w);

    float acc[LOW_LEVELS * 2];
#pragma unroll
    for (int l = 0; l < 6; l++)
        level_lerp(tables, l, px, py, pz, acc[l * 2 + 0], acc[l * 2 + 1]);
#pragma unroll
    for (int l = 6; l < LOW_LEVELS; l++)
        level_lerp_paired(tables, l, px, py, pz, acc[l * 2 + 0], acc[l * 2 + 1]);

    float4* __restrict__ o4 = reinterpret_cast<float4*>(out + (size_t)n * (N_LEVELS * 2));
#pragma unroll
    for (int i = 0; i < LOW_LEVELS / 2; i++)
        o4[i] = make_float4(acc[i * 4 + 0], acc[i * 4 + 1], acc[i * 4 + 2], acc[i * 4 + 3]);
}

// Levels 8..11, original order (random), paired gathers. Writes sector 2 (32B).
__global__ __launch_bounds__(256) void high_kernel(
    const float* __restrict__ x,
    const float* __restrict__ tables, float* __restrict__ out)
{
    int n = blockIdx.x * blockDim.x + threadIdx.x;
    if (n >= N_PTS) return;

    const float px = x[n * 3 + 0];
    const float py = x[n * 3 + 1];
    const float pz = x[n * 3 + 2];

    float acc[(N_LEVELS - LOW_LEVELS) * 2];
#pragma unroll
    for (int l = LOW_LEVELS; l < N_LEVELS; l++)
        level_lerp_paired(tables, l, px, py, pz,
                          acc[(l - LOW_LEVELS) * 2 + 0], acc[(l - LOW_LEVELS) * 2 + 1]);

    float4* __restrict__ o4 =
        reinterpret_cast<float4*>(out + (size_t)n * (N_LEVELS * 2) + LOW_LEVELS * 2);
#pragma unroll
    for (int i = 0; i < (N_LEVELS - LOW_LEVELS) / 2; i++)
        o4[i] = make_float4(acc[i * 4 + 0], acc[i * 4 + 1], acc[i * 4 + 2], acc[i * 4 + 3]);
}

// ---------------------------------------------------------------------------
extern "C" void kernel_launch(void* const* d_in, const int* in_sizes, int n_in,
                              void* d_out, int out_size) {
    const float* x = (const float*)d_in[0];
    const float* tables = (const float*)d_in[1];
    float* out = (float*)d_out;

    static cudaStream_t s2 = nullptr;
    static cudaEvent_t ev_fork = nullptr, ev_join = nullptr;
    if (s2 == nullptr) {
        cudaStreamCreateWithFlags(&s2, cudaStreamNonBlocking);
        cudaEventCreateWithFlags(&ev_fork, cudaEventDisableTiming);
        cudaEventCreateWithFlags(&ev_join, cudaEventDisableTiming);
    }

    const int threads = 256;
    const int blocks = (N_PTS + threads - 1) / threads;

    cudaEventRecord(ev_fork, 0);
    cudaStreamWaitEvent(s2, ev_fork, 0);
    high_kernel<<<blocks, threads, 0, s2>>>(x, tables, out);

    zero_cursor_kernel<<<(NBINS + 255) / 256, 256>>>();
    scatter_kernel<<<blocks, threads>>>(x);
    low_kernel<<<PAD_SLOTS / threads, threads>>>(tables, out);

    cudaEventRecord(ev_join, s2);
    cudaStreamWaitEvent(0, ev_join, 0);
}

// round 15
// speedup vs baseline: 1.5410x; 1.5410x over previous
#include <cuda_runtime.h>
#include <cstdint>

#define N_LEVELS 12
#define LOG2_T 19
#define T_SIZE (1u << LOG2_T)
#define T_MASK (T_SIZE - 1u)
#define N_PTS 1048576

#define LOW_LEVELS 8   // sector-aligned output split: 64B low / 32B high

#define BIN_BITS 5
#define BIN_RES (1 << BIN_BITS)      // 32
#define NBINS (1 << (3 * BIN_BITS))  // 32768
#define BIN_CAP 128
#define PAD_SLOTS (NBINS * BIN_CAP)  // 4M

#define P1 2654435761u
#define P2 805459861u

__constant__ float c_res[N_LEVELS] = {
    16.f, 22.f, 30.f, 42.f, 58.f, 80.f, 110.f, 152.f, 210.f, 290.f, 400.f, 553.f
};

__device__ uint32_t g_cursor[NBINS];
__device__ float4   g_pad[PAD_SLOTS];

// ---------------------------------------------------------------------------
__device__ __forceinline__ uint32_t expand5(uint32_t v) {
    v = (v | (v << 8)) & 0x0000F00Fu;
    v = (v | (v << 4)) & 0x000C30C3u;
    v = (v | (v << 2)) & 0x00249249u;
    return v;
}

__device__ __forceinline__ uint32_t bin_id(float px, float py, float pz) {
    uint32_t bx = min((uint32_t)(px * BIN_RES), (uint32_t)(BIN_RES - 1));
    uint32_t by = min((uint32_t)(py * BIN_RES), (uint32_t)(BIN_RES - 1));
    uint32_t bz = min((uint32_t)(pz * BIN_RES), (uint32_t)(BIN_RES - 1));
    return expand5(bx) | (expand5(by) << 1) | (expand5(bz) << 2);
}

// ---------------------------------------------------------------------------
__global__ void zero_cursor_kernel() {
    int i = blockIdx.x * blockDim.x + threadIdx.x;
    if (i < NBINS) g_cursor[i] = 0u;
}

__global__ __launch_bounds__(256) void scatter_kernel(const float* __restrict__ x) {
    int n = blockIdx.x * blockDim.x + threadIdx.x;
    if (n >= N_PTS) return;
    float px = x[n * 3 + 0];
    float py = x[n * 3 + 1];
    float pz = x[n * 3 + 2];
    uint32_t b = bin_id(px, py, pz);
    uint32_t pos = atomicAdd(&g_cursor[b], 1u);
    if (pos < BIN_CAP)
        g_pad[b * BIN_CAP + pos] = make_float4(px, py, pz, __int_as_float(n));
}

// ---------------------------------------------------------------------------
__device__ __forceinline__ void tri_weights(
    float wx, float wy, float wz,
    float& w000, float& w100, float& w010, float& w110,
    float& w001, float& w101, float& w011, float& w111)
{
    const float ux = 1.f - wx;
    const float uy = 1.f - wy;
    const float uz = 1.f - wz;
    const float w00 = uy * uz;
    const float w10 = wy * uz;
    const float w01 = uy * wz;
    const float w11 = wy * wz;
    w000 = ux * w00;  w100 = wx * w00;
    w010 = ux * w10;  w110 = wx * w10;
    w001 = ux * w01;  w101 = wx * w01;
    w011 = ux * w11;  w111 = wx * w11;
}

// Simple 8-gather trilerp — for the sorted (low) kernel. Issue-lean.
__device__ __forceinline__ void level_lerp(
    const float* __restrict__ tables, int l,
    float px, float py, float pz, float& a0, float& a1)
{
    const float res = c_res[l];
    const float sx = px * res, sy = py * res, sz = pz * res;
    const float fx = floorf(sx), fy = floorf(sy), fz = floorf(sz);
    const float wx = sx - fx, wy = sy - fy, wz = sz - fz;

    const uint32_t x0 = (uint32_t)fx;
    const uint32_t hy0 = (uint32_t)fy * P1;
    const uint32_t hy1 = hy0 + P1;
    const uint32_t hz0 = (uint32_t)fz * P2;
    const uint32_t hz1 = hz0 + P2;
    const uint32_t hx0 = x0;
    const uint32_t hx1 = x0 + 1u;

    const float2* __restrict__ tab =
        reinterpret_cast<const float2*>(tables) + (size_t)l * T_SIZE;

    const float2 f000 = __ldg(&tab[(hx0 ^ hy0 ^ hz0) & T_MASK]);
    const float2 f100 = __ldg(&tab[(hx1 ^ hy0 ^ hz0) & T_MASK]);
    const float2 f010 = __ldg(&tab[(hx0 ^ hy1 ^ hz0) & T_MASK]);
    const float2 f110 = __ldg(&tab[(hx1 ^ hy1 ^ hz0) & T_MASK]);
    const float2 f001 = __ldg(&tab[(hx0 ^ hy0 ^ hz1) & T_MASK]);
    const float2 f101 = __ldg(&tab[(hx1 ^ hy0 ^ hz1) & T_MASK]);
    const float2 f011 = __ldg(&tab[(hx0 ^ hy1 ^ hz1) & T_MASK]);
    const float2 f111 = __ldg(&tab[(hx1 ^ hy1 ^ hz1) & T_MASK]);

    float w000, w100, w010, w110, w001, w101, w011, w111;
    tri_weights(wx, wy, wz, w000, w100, w010, w110, w001, w101, w011, w111);

    a0 = w000 * f000.x;            a1 = w000 * f000.y;
    a0 = fmaf(w100, f100.x, a0);   a1 = fmaf(w100, f100.y, a1);
    a0 = fmaf(w010, f010.x, a0);   a1 = fmaf(w010, f010.y, a1);
    a0 = fmaf(w110, f110.x, a0);   a1 = fmaf(w110, f110.y, a1);
    a0 = fmaf(w001, f001.x, a0);   a1 = fmaf(w001, f001.y, a1);
    a0 = fmaf(w101, f101.x, a0);   a1 = fmaf(w101, f101.y, a1);
    a0 = fmaf(w011, f011.x, a0);   a1 = fmaf(w011, f011.y, a1);
    a0 = fmaf(w111, f111.x, a0);   a1 = fmaf(w111, f111.y, a1);
}

// Paired-gather trilerp — ONLY for the random (high) kernel.
__device__ __forceinline__ void level_lerp_paired(
    const float* __restrict__ tables, int l,
    float px, float py, float pz, float& a0, float& a1)
{
    const float res = c_res[l];
    const float sx = px * res, sy = py * res, sz = pz * res;
    const float fx = floorf(sx), fy = floorf(sy), fz = floorf(sz);
    const float wx = sx - fx, wy = sy - fy, wz = sz - fz;

    const uint32_t x0 = (uint32_t)fx;
    const uint32_t hy0 = (uint32_t)fy * P1;
    const uint32_t hy1 = hy0 + P1;
    const uint32_t hz0 = (uint32_t)fz * P2;
    const uint32_t hz1 = hz0 + P2;

    const uint32_t s00 = hy0 ^ hz0;
    const uint32_t s10 = hy1 ^ hz0;
    const uint32_t s01 = hy0 ^ hz1;
    const uint32_t s11 = hy1 ^ hz1;

    const float2* __restrict__ tab =
        reinterpret_cast<const float2*>(tables) + (size_t)l * T_SIZE;

    float2 f000, f100, f010, f110, f001, f101, f011, f111;

    if ((x0 & 1u) == 0u) {
        const float4* __restrict__ tab4 = reinterpret_cast<const float4*>(tab);
#define PAIR4(s, lo, hi)                                                    \
        {                                                                   \
            const uint32_t h = (x0 ^ (s)) & T_MASK;                         \
            const float4 v = __ldg(&tab4[h >> 1]);                          \
            const float2 e0 = make_float2(v.x, v.y);                        \
            const float2 e1 = make_float2(v.z, v.w);                        \
            if (h & 1u) { lo = e1; hi = e0; } else { lo = e0; hi = e1; }    \
        }
        PAIR4(s00, f000, f100)
        PAIR4(s10, f010, f110)
        PAIR4(s01, f001, f101)
        PAIR4(s11, f011, f111)
#undef PAIR4
    } else {
        const uint32_t hx0 = x0;
        const uint32_t hx1 = x0 + 1u;
        f000 = __ldg(&tab[(hx0 ^ s00) & T_MASK]);
        f100 = __ldg(&tab[(hx1 ^ s00) & T_MASK]);
        f010 = __ldg(&tab[(hx0 ^ s10) & T_MASK]);
        f110 = __ldg(&tab[(hx1 ^ s10) & T_MASK]);
        f001 = __ldg(&tab[(hx0 ^ s01) & T_MASK]);
        f101 = __ldg(&tab[(hx1 ^ s01) & T_MASK]);
        f011 = __ldg(&tab[(hx0 ^ s11) & T_MASK]);
        f111 = __ldg(&tab[(hx1 ^ s11) & T_MASK]);
    }

    float w000, w100, w010, w110, w001, w101, w011, w111;
    tri_weights(wx, wy, wz, w000, w100, w010, w110, w001, w101, w011, w111);

    a0 = w000 * f000.x;            a1 = w000 * f000.y;
    a0 = fmaf(w100, f100.x, a0);   a1 = fmaf(w100, f100.y, a1);
    a0 = fmaf(w010, f010.x, a0);   a1 = fmaf(w010, f010.y, a1);
    a0 = fmaf(w110, f110.x, a0);   a1 = fmaf(w110, f110.y, a1);
    a0 = fmaf(w001, f001.x, a0);   a1 = fmaf(w001, f001.y, a1);
    a0 = fmaf(w101, f101.x, a0);   a1 = fmaf(w101, f101.y, a1);
    a0 = fmaf(w011, f011.x, a0);   a1 = fmaf(w011, f011.y, a1);
    a0 = fmaf(w111, f111.x, a0);   a1 = fmaf(w111, f111.y, a1);
}

// Levels 0..7 over padded buckets (sorted, ALL simple gathers — R10 form).
__global__ __launch_bounds__(256) void low_kernel(
    const float* __restrict__ tables, float* __restrict__ out)
{
    int j = blockIdx.x * blockDim.x + threadIdx.x;
    const uint32_t bin = (uint32_t)j >> 7;
    const uint32_t slot = (uint32_t)j & (BIN_CAP - 1);

    const uint32_t cnt = g_cursor[bin];
    if (slot >= cnt) return;

    const float4 s = g_pad[j];
    const float px = s.x, py = s.y, pz = s.z;
    const int n = __float_as_int(s.w);

    float acc[LOW_LEVELS * 2];
#pragma unroll
    for (int l = 0; l < LOW_LEVELS; l++)
        level_lerp(tables, l, px, py, pz, acc[l * 2 + 0], acc[l * 2 + 1]);

    float4* __restrict__ o4 = reinterpret_cast<float4*>(out + (size_t)n * (N_LEVELS * 2));
#pragma unroll
    for (int i = 0; i < LOW_LEVELS / 2; i++)
        o4[i] = make_float4(acc[i * 4 + 0], acc[i * 4 + 1], acc[i * 4 + 2], acc[i * 4 + 3]);
}

// Levels 8..11, consecutive rows, paired gathers. smem-staged coalesced I/O:
// x reads 9wf->3wf per warp; out writes 64wf->24wf per warp.
__global__ __launch_bounds__(256) void high_kernel(
    const float* __restrict__ x,
    const float* __restrict__ tables, float* __restrict__ out)
{
    __shared__ float4 sbuf[512];                 // 8KB, reused x-stage -> out-stage
    float* sf = reinterpret_cast<float*>(sbuf);

    const int tid = threadIdx.x;
    const int base = blockIdx.x * 256;           // N_PTS % 256 == 0: full blocks

    // Stage x: 256 pts * 3 floats = 768 floats = 192 float4, coalesced.
    {
        const float4* __restrict__ x4 =
            reinterpret_cast<const float4*>(x + (size_t)base * 3);
        if (tid < 192) sbuf[tid] = __ldg(&x4[tid]);
    }
    __syncthreads();
    const float px = sf[tid * 3 + 0];   // gcd(3,32)=1 -> conflict-free
    const float py = sf[tid * 3 + 1];
    const float pz = sf[tid * 3 + 2];
    __syncthreads();                    // all reads done before stage reuse

    float acc[(N_LEVELS - LOW_LEVELS) * 2];
#pragma unroll
    for (int l = LOW_LEVELS; l < N_LEVELS; l++)
        level_lerp_paired(tables, l, px, py, pz,
                          acc[(l - LOW_LEVELS) * 2 + 0], acc[(l - LOW_LEVELS) * 2 + 1]);

    // Stage results chunk-major: chunk k = (point k/2, half k%2).
    sbuf[tid * 2 + 0] = make_float4(acc[0], acc[1], acc[2], acc[3]);
    sbuf[tid * 2 + 1] = make_float4(acc[4], acc[5], acc[6], acc[7]);
    __syncthreads();

    // Interleaved store: each STG.128 covers 16 consecutive rows (12 lines).
#pragma unroll
    for (int k = tid; k < 512; k += 256) {
        const int p = k >> 1;
        const int h = k & 1;
        *reinterpret_cast<float4*>(
            out + (size_t)(base + p) * (N_LEVELS * 2) + LOW_LEVELS * 2 + h * 4) = sbuf[k];
    }
}

// ---------------------------------------------------------------------------
extern "C" void kernel_launch(void* const* d_in, const int* in_sizes, int n_in,
                              void* d_out, int out_size) {
    const float* x = (const float*)d_in[0];
    const float* tables = (const float*)d_in[1];
    float* out = (float*)d_out;

    static cudaStream_t s2 = nullptr;
    static cudaEvent_t ev_fork = nullptr, ev_join = nullptr;
    if (s2 == nullptr) {
        cudaStreamCreateWithFlags(&s2, cudaStreamNonBlocking);
        cudaEventCreateWithFlags(&ev_fork, cudaEventDisableTiming);
        cudaEventCreateWithFlags(&ev_join, cudaEventDisableTiming);
    }

    const int threads = 256;
    const int blocks = (N_PTS + threads - 1) / threads;

    cudaEventRecord(ev_fork, 0);
    cudaStreamWaitEvent(s2, ev_fork, 0);
    high_kernel<<<blocks, threads, 0, s2>>>(x, tables, out);

    zero_cursor_kernel<<<(NBINS + 255) / 256, 256>>>();
    scatter_kernel<<<blocks, threads>>>(x);
    low_kernel<<<PAD_SLOTS / threads, threads>>>(tables, out);

    cudaEventRecord(ev_join, s2);
    cudaStreamWaitEvent(0, ev_join, 0);
}